// round 1
// baseline (speedup 1.0000x reference)
#include <cuda_runtime.h>

#define TPB 256
#define LDH 132            // padded row stride for 128-wide smem matrices
#define K0  648

// ---------------------------------------------------------------------------
// One CTA = 128 positions (fixed (ahi,awi), 4 consecutive h rows, all 32 w).
// Phase A: base[128,128] = q_feat @ W0[:648]  (implicit-GEMM gather of A tiles)
// Branches i=0..3: h1 = relu(base + b0 + s*(32^(i+1)*(W0_716+W0_717)+(W0_718+W0_719)))
//                  h2 = relu(h1@W1+b1); h3 = relu(h2@W2+b2); y += 0.25*(h3@W3+b3)
// Scatter y with pixel-shuffle indexing.
// ---------------------------------------------------------------------------

__device__ __forceinline__ void gemm_layer(
    const float* __restrict__ src,      // smem [128][LDH]
    const float* __restrict__ Wg,       // global [128][128]
    const float* __restrict__ bias,     // smem [128]
    float* __restrict__ dst,            // smem [128][LDH]
    float* __restrict__ sB,             // smem staging [8][128]
    int tx, int ty, int tid)
{
    float a2[8][8];
#pragma unroll
    for (int i = 0; i < 8; i++)
#pragma unroll
        for (int j = 0; j < 8; j++) a2[i][j] = 0.f;

    for (int kc = 0; kc < 16; kc++) {
        // stage W chunk [8][128]
        {
            int k = tid >> 5, j = (tid & 31) * 4;
            *(float4*)&sB[k * 128 + j] = *(const float4*)&Wg[(kc * 8 + k) * 128 + j];
        }
        __syncthreads();
#pragma unroll
        for (int k2 = 0; k2 < 8; k2++) {
            int kk = kc * 8 + k2;
            float av[8];
#pragma unroll
            for (int i = 0; i < 8; i++) av[i] = src[(ty * 8 + i) * LDH + kk];
            float4 bb0 = *(float4*)&sB[k2 * 128 + tx * 8];
            float4 bb1 = *(float4*)&sB[k2 * 128 + tx * 8 + 4];
            float bv[8] = {bb0.x, bb0.y, bb0.z, bb0.w, bb1.x, bb1.y, bb1.z, bb1.w};
#pragma unroll
            for (int i = 0; i < 8; i++)
#pragma unroll
                for (int j = 0; j < 8; j++) a2[i][j] = fmaf(av[i], bv[j], a2[i][j]);
        }
        __syncthreads();
    }
    // epilogue: relu + bias
#pragma unroll
    for (int i = 0; i < 8; i++) {
        int r = ty * 8 + i;
        float4 v0, v1;
        v0.x = fmaxf(a2[i][0] + bias[tx * 8 + 0], 0.f);
        v0.y = fmaxf(a2[i][1] + bias[tx * 8 + 1], 0.f);
        v0.z = fmaxf(a2[i][2] + bias[tx * 8 + 2], 0.f);
        v0.w = fmaxf(a2[i][3] + bias[tx * 8 + 3], 0.f);
        v1.x = fmaxf(a2[i][4] + bias[tx * 8 + 4], 0.f);
        v1.y = fmaxf(a2[i][5] + bias[tx * 8 + 5], 0.f);
        v1.z = fmaxf(a2[i][6] + bias[tx * 8 + 6], 0.f);
        v1.w = fmaxf(a2[i][7] + bias[tx * 8 + 7], 0.f);
        *(float4*)&dst[r * LDH + tx * 8]     = v0;
        *(float4*)&dst[r * LDH + tx * 8 + 4] = v1;
    }
}

__global__ __launch_bounds__(TPB, 1)
void inr_fused_kernel(const float* __restrict__ inp,
                      const float* __restrict__ W0, const float* __restrict__ b0,
                      const float* __restrict__ W1, const float* __restrict__ b1,
                      const float* __restrict__ W2, const float* __restrict__ b2,
                      const float* __restrict__ W3, const float* __restrict__ b3,
                      float* __restrict__ outp)
{
    extern __shared__ float sm[];
    float* sBase = sm;                       // 128*LDH
    float* sX    = sBase + 128 * LDH;        // 128*LDH
    float* sY    = sX + 128 * LDH;           // 128*LDH
    float* sA    = sY + 128 * LDH;           // 8*128 (gathered A chunk)
    float* sB    = sA + 8 * 128;             // 8*128 (weight chunk)
    float* sW3   = sB + 8 * 128;             // 128*12
    float* sb0   = sW3 + 128 * 12;           // 128
    float* sb1   = sb0 + 128;
    float* sb2   = sb1 + 128;
    float* sP    = sb2 + 128;                // W0[716]+W0[717]
    float* sQ    = sP + 128;                 // W0[718]+W0[719]
    float* sb3   = sQ + 128;                 // 16
    int2*  sLut  = (int2*)(sb3 + 16);        // 648 entries

    const int tid = threadIdx.x;
    const int tx = tid & 15, ty = tid >> 4;

    const int blk  = blockIdx.x;
    const int ablk = blk >> 3;               // 0..48 -> (ahi,awi)
    const int hgrp = blk & 7;                // 0..7  -> hi group of 4
    const int ahi  = ablk / 7;
    const int awi  = ablk % 7;
    const int inpBase = ahi * 7168 + awi * 1024 + hgrp * 128;

    // ---- init LUT + constants ----
    for (int k = tid; k < K0; k += TPB) {
        int aj = k % 3, ai = (k / 3) % 3, kj = (k / 9) % 3, ki = (k / 27) % 3, ch = k / 81;
        int off = ch * 50176 + (ai - 1) * 7168 + (aj - 1) * 1024 + (ki - 1) * 32 + (kj - 1);
        sLut[k] = make_int2(off, ai | (aj << 4) | (ki << 8) | (kj << 12));
    }
    for (int c = tid; c < 128; c += TPB) {
        sb0[c] = b0[c]; sb1[c] = b1[c]; sb2[c] = b2[c];
        sP[c] = W0[716 * 128 + c] + W0[717 * 128 + c];
        sQ[c] = W0[718 * 128 + c] + W0[719 * 128 + c];
    }
    for (int e = tid; e < 128 * 12; e += TPB) sW3[e] = W3[e];
    if (tid < 12) sb3[tid] = b3[tid];
    __syncthreads();

    // ---------------- Phase A: base = q_feat @ W0[:648] ----------------
    float acc[8][8];
#pragma unroll
    for (int i = 0; i < 8; i++)
#pragma unroll
        for (int j = 0; j < 8; j++) acc[i][j] = 0.f;

    for (int kc = 0; kc < 81; kc++) {
        // stage gathered A chunk [8][128] + W0 chunk [8][128]
        {
            int e = tid;
#pragma unroll
            for (int t = 0; t < 4; t++, e += TPB) {
                int k = e >> 7, m = e & 127;
                int kg = kc * 8 + k;
                int2 lu = sLut[kg];
                int ai = lu.y & 15, aj = (lu.y >> 4) & 15, ki = (lu.y >> 8) & 15, kj = (lu.y >> 12) & 15;
                int hi = hgrp * 4 + (m >> 5), wi = m & 31;
                bool ok = (unsigned)(ahi + ai - 1) < 7u && (unsigned)(awi + aj - 1) < 7u
                       && (unsigned)(hi + ki - 1) < 32u && (unsigned)(wi + kj - 1) < 32u;
                sA[k * 128 + m] = ok ? inp[inpBase + m + lu.x] : 0.f;
            }
            int k = tid >> 5, j = (tid & 31) * 4;
            *(float4*)&sB[k * 128 + j] = *(const float4*)&W0[(kc * 8 + k) * 128 + j];
        }
        __syncthreads();
#pragma unroll
        for (int k = 0; k < 8; k++) {
            float4 a0v = *(float4*)&sA[k * 128 + ty * 8];
            float4 a1v = *(float4*)&sA[k * 128 + ty * 8 + 4];
            float4 bb0 = *(float4*)&sB[k * 128 + tx * 8];
            float4 bb1 = *(float4*)&sB[k * 128 + tx * 8 + 4];
            float av[8] = {a0v.x, a0v.y, a0v.z, a0v.w, a1v.x, a1v.y, a1v.z, a1v.w};
            float bv[8] = {bb0.x, bb0.y, bb0.z, bb0.w, bb1.x, bb1.y, bb1.z, bb1.w};
#pragma unroll
            for (int i = 0; i < 8; i++)
#pragma unroll
                for (int j = 0; j < 8; j++) acc[i][j] = fmaf(av[i], bv[j], acc[i][j]);
        }
        __syncthreads();
    }
    // park base in smem (frees the 64 accumulator regs for branch GEMMs)
#pragma unroll
    for (int i = 0; i < 8; i++) {
        *(float4*)&sBase[(ty * 8 + i) * LDH + tx * 8]     = make_float4(acc[i][0], acc[i][1], acc[i][2], acc[i][3]);
        *(float4*)&sBase[(ty * 8 + i) * LDH + tx * 8 + 4] = make_float4(acc[i][4], acc[i][5], acc[i][6], acc[i][7]);
    }
    __syncthreads();

    // ---------------- 4 branches ----------------
    float y6[6] = {0.f, 0.f, 0.f, 0.f, 0.f, 0.f};
    float powv = 32.f;
    for (int br = 0; br < 4; br++) {
        // h1 = relu(base + b0 + s * (powv*P + Q))  -> sX
#pragma unroll
        for (int i = 0; i < 8; i++) {
            int r = ty * 8 + i;
            float s = 1.f;
            if (hgrp == 0 && r < 4) s = (r < 2) ? 0.0625f : (2.f / 7.f);
#pragma unroll
            for (int j = 0; j < 8; j++) {
                int c = tx * 8 + j;
                float u = sBase[r * LDH + c] + sb0[c] + s * fmaf(powv, sP[c], sQ[c]);
                sX[r * LDH + c] = fmaxf(u, 0.f);
            }
        }
        __syncthreads();

        gemm_layer(sX, W1, sb1, sY, sB, tx, ty, tid);   // h2 -> sY
        __syncthreads();
        gemm_layer(sY, W2, sb2, sX, sB, tx, ty, tid);   // h3 -> sX
        __syncthreads();

        // y += 0.25 * (h3 @ W3 + b3)
#pragma unroll
        for (int s6 = 0; s6 < 6; s6++) {
            int p = tid * 6 + s6;
            int r = p / 12, c = p % 12;
            float a = sb3[c];
#pragma unroll 8
            for (int k = 0; k < 128; k++)
                a = fmaf(sX[r * LDH + k], sW3[k * 12 + c], a);
            y6[s6] += 0.25f * a;
        }
        __syncthreads();
        powv *= 32.f;
    }

    // ---------------- scatter with pixel shuffle ----------------
#pragma unroll
    for (int s6 = 0; s6 < 6; s6++) {
        int p = tid * 6 + s6;
        int r = p / 12, c = p % 12;
        int hi = hgrp * 4 + (r >> 5), wi = r & 31;
        int rgb = c >> 2, pr = (c >> 1) & 1, qc = c & 1;
        outp[rgb * 200704 + ahi * 28672 + awi * 4096 + (2 * hi + pr) * 64 + (2 * wi + qc)] = y6[s6];
    }
}

extern "C" void kernel_launch(void* const* d_in, const int* in_sizes, int n_in,
                              void* d_out, int out_size)
{
    (void)in_sizes; (void)n_in; (void)out_size;
    const float* inp = (const float*)d_in[0];
    const float* W0  = (const float*)d_in[1];
    const float* b0  = (const float*)d_in[2];
    const float* W1  = (const float*)d_in[3];
    const float* b1  = (const float*)d_in[4];
    const float* W2  = (const float*)d_in[5];
    const float* b2  = (const float*)d_in[6];
    const float* W3  = (const float*)d_in[7];
    const float* b3  = (const float*)d_in[8];
    float* outp = (float*)d_out;

    // smem: 3*128*132 + 2*8*128 + 128*12 + 3*128 + 2*128 + 16 + 648*2(int2->floats)
    size_t smem_floats = 3 * 128 * LDH + 2 * 8 * 128 + 128 * 12 + 5 * 128 + 16 + 648 * 2;
    size_t smem = smem_floats * sizeof(float);

    cudaFuncSetAttribute(inr_fused_kernel,
                         cudaFuncAttributeMaxDynamicSharedMemorySize, (int)smem);

    inr_fused_kernel<<<392, TPB, smem>>>(inp, W0, b0, W1, b1, W2, b2, W3, b3, outp);
}